// round 9
// baseline (speedup 1.0000x reference)
#include <cuda_runtime.h>
#include <math.h>

// GRU problem constants
#define T_SEQ 1024
#define BATCH 32
#define HID   512
#define H3    1536   // 3*HID
#define LAYERS 3

// ---------------------------------------------------------------------------
// Scratch (device globals — no runtime allocation allowed)
// ---------------------------------------------------------------------------
__device__ float g_xi[2][T_SEQ][H3][BATCH];     // [dir][t][gate_row][batch]
__device__ float g_y[2][T_SEQ][BATCH][2 * HID]; // layer outputs (2 buffers)
__device__ float g_h[2][2][BATCH][HID];         // h double buffer [buf][dir][b][k]
__device__ int   g_flag[2][64];                 // per-dir, per-CTA epoch flags

// ---------------------------------------------------------------------------
// f32x2 packed-FMA helpers (sm_100+; only reachable via PTX)
// ---------------------------------------------------------------------------
__device__ __forceinline__ unsigned long long dup2(float x) {
    unsigned long long r;
    asm("mov.b64 %0, {%1, %1};" : "=l"(r) : "f"(x));
    return r;
}
__device__ __forceinline__ void ffma2(unsigned long long& d,
                                      unsigned long long a,
                                      unsigned long long b) {
    asm("fma.rn.f32x2 %0, %1, %2, %0;" : "+l"(d) : "l"(a), "l"(b));
}
__device__ __forceinline__ float2 unpk(unsigned long long v) {
    float2 f;
    asm("mov.b64 {%0, %1}, %2;" : "=f"(f.x), "=f"(f.y) : "l"(v));
    return f;
}

// ---------------------------------------------------------------------------
// Zero the flag array (runs once per graph replay, before gru0)
// ---------------------------------------------------------------------------
__global__ void zero_bar_kernel() {
    int i = threadIdx.x;
    if (i < 128) ((int*)g_flag)[i] = 0;
}

// ---------------------------------------------------------------------------
// Input projection v2: Xi[d][t][g][b] = sum_k A[(t,b),k]*W[d][g][k] + b_ih[d][g]
// 128x128 tile, 512 threads, 4m x 8j per thread (16 f32x2 accumulators),
// register double-buffered global loads, f32x2 packed FMA.
// Low register footprint (~70) -> no spills, 16 warps/SM.
// ---------------------------------------------------------------------------
__global__ __launch_bounds__(512) void proj_kernel(
    const float* __restrict__ x0,
    const float* __restrict__ W,      // (2, 1536, K)
    const float* __restrict__ bih,    // (2, 1536)
    int K, int src)
{
    const float* A = (src == 0) ? x0 : &g_y[src - 1][0][0][0];

    int d  = blockIdx.z;
    int n0 = blockIdx.x * 128;  // gate-row tile
    int m0 = blockIdx.y * 128;  // (t,b) row tile
    const float* Wd = W + (size_t)d * H3 * K;
    const float* bd = bih + d * H3;

    __shared__ float As[16][128];
    __shared__ float Bs[16][128];

    int tid = threadIdx.x;
    int tx  = tid & 15;         // j-group (8 j: {tx*4..+3, 64+tx*4..+3})
    int ty  = tid >> 4;         // m-group (4 m: ty*4..+3)

    // Staging indices: 512 float4s per array per k0, one per thread
    int lrow = tid >> 2;        // 0..127
    int lq   = (tid & 3) << 2;  // 0,4,8,12

    const float* Aptr = &A [(size_t)(m0 + lrow) * K + lq];
    const float* Wptr = &Wd[(size_t)(n0 + lrow) * K + lq];

    unsigned long long acc[4][4];
#pragma unroll
    for (int i = 0; i < 4; i++)
#pragma unroll
        for (int j = 0; j < 4; j++) acc[i][j] = 0ull;

    // Prime the double buffer
    float4 a_nx = *(const float4*)Aptr;
    float4 b_nx = *(const float4*)Wptr;

    for (int k0 = 0; k0 < K; k0 += 16) {
        As[lq + 0][lrow] = a_nx.x; As[lq + 1][lrow] = a_nx.y;
        As[lq + 2][lrow] = a_nx.z; As[lq + 3][lrow] = a_nx.w;
        Bs[lq + 0][lrow] = b_nx.x; Bs[lq + 1][lrow] = b_nx.y;
        Bs[lq + 2][lrow] = b_nx.z; Bs[lq + 3][lrow] = b_nx.w;
        __syncthreads();

        // Kick off next tile's global loads (overlap with compute below)
        if (k0 + 16 < K) {
            a_nx = *(const float4*)(Aptr + k0 + 16);
            b_nx = *(const float4*)(Wptr + k0 + 16);
        }

#pragma unroll
        for (int kk = 0; kk < 16; kk++) {
            float4 af = *(const float4*)&As[kk][ty * 4];          // broadcast
            ulonglong2 b0 = *(const ulonglong2*)&Bs[kk][tx * 4];
            ulonglong2 b1 = *(const ulonglong2*)&Bs[kk][64 + tx * 4];
            unsigned long long a0 = dup2(af.x);
            unsigned long long a1 = dup2(af.y);
            unsigned long long a2 = dup2(af.z);
            unsigned long long a3 = dup2(af.w);
            ffma2(acc[0][0], a0, b0.x); ffma2(acc[0][1], a0, b0.y);
            ffma2(acc[0][2], a0, b1.x); ffma2(acc[0][3], a0, b1.y);
            ffma2(acc[1][0], a1, b0.x); ffma2(acc[1][1], a1, b0.y);
            ffma2(acc[1][2], a1, b1.x); ffma2(acc[1][3], a1, b1.y);
            ffma2(acc[2][0], a2, b0.x); ffma2(acc[2][1], a2, b0.y);
            ffma2(acc[2][2], a2, b1.x); ffma2(acc[2][3], a2, b1.y);
            ffma2(acc[3][0], a3, b0.x); ffma2(acc[3][1], a3, b0.y);
            ffma2(acc[3][2], a3, b1.x); ffma2(acc[3][3], a3, b1.y);
        }
        __syncthreads();
    }

#pragma unroll
    for (int i = 0; i < 4; i++) {
        int m = m0 + ty * 4 + i;
        int t = m >> 5;
        int b = m & 31;
#pragma unroll
        for (int jp = 0; jp < 4; jp++) {
            int g = n0 + ((jp < 2) ? (tx * 4 + jp * 2)
                                   : (64 + tx * 4 + (jp - 2) * 2));
            float2 c = unpk(acc[i][jp]);
            g_xi[d][t][g + 0][b] = c.x + bd[g + 0];
            g_xi[d][t][g + 1][b] = c.y + bd[g + 1];
        }
    }
}

// ---------------------------------------------------------------------------
// Persistent recurrent kernel (unchanged from R8 — known correct).
// grid (64,2) = 128 CTAs (1/SM), 256 threads; 2-D lane map (8 b x 4 j).
// ---------------------------------------------------------------------------
#define P_H 516   // padded row stride (floats) -> conflict-free LDS.128
#define GRU_SMEM ((3 * 8 * P_H + BATCH * P_H) * 4)

__global__ __launch_bounds__(256) void gru_layer_kernel(
    const float* __restrict__ whh,   // (2, 1536, 512)
    const float* __restrict__ bhh,   // (2, 1536)
    float* __restrict__ dout,        // (6, 32, 512)
    int layer, int ydst)
{
    extern __shared__ float sm[];
    float* sW = sm;                  // [3][8][516]
    float* sH = sm + 3 * 8 * P_H;    // [32][516]

    int d   = blockIdx.y;
    int j0  = blockIdx.x * 8;
    int tid = threadIdx.x;
    int w   = tid >> 5;
    int l   = tid & 31;
    int lb  = l & 7;
    int lj  = l >> 3;
    int b   = (w & 3) * 8 + lb;      // 0..31
    int jr  = (w >> 2) * 4 + lj;     // 0..7
    int j   = j0 + jr;

    // ---- Stage W_hh rows {j0..j0+7} x 3 gates (once per layer) ----
    const float* wd = whh + (size_t)d * H3 * HID;
#pragma unroll
    for (int it = 0; it < 12; it++) {
        int idx  = it * 256 + tid;       // float4 units, 0..3071
        int row  = idx >> 7;             // 0..23
        int q    = (idx & 127) << 2;
        int gate = row >> 3;
        int r    = row & 7;
        *(float4*)&sW[(gate * 8 + r) * P_H + q] =
            *(const float4*)&wd[(size_t)(gate * 512 + j0 + r) * 512 + q];
    }
    const float* bd = bhh + d * H3;
    float br = bd[j], bz = bd[512 + j], bn = bd[1024 + j];

    const float* wr_ = &sW[(0 * 8 + jr) * P_H];
    const float* wz_ = &sW[(1 * 8 + jr) * P_H];
    const float* wn_ = &sW[(2 * 8 + jr) * P_H];
    const float* hb  = &sH[b * P_H];
    __syncthreads();

    float hold = 0.f;
    int t0 = d ? (T_SEQ - 1) : 0;
    float xr = g_xi[d][t0][j][b];
    float xz = g_xi[d][t0][512 + j][b];
    float xn = g_xi[d][t0][1024 + j][b];

    for (int s = 0; s < T_SEQ; s++) {
        int t = d ? (T_SEQ - 1 - s) : s;

        float ar = 0.f, az = 0.f, an = 0.f;
        if (s > 0) {
            // Stage h: 32*512 floats = 4096 float4 -> 16 iters * 256 threads
            const float* hin = &g_h[s & 1][d][0][0];
#pragma unroll
            for (int it = 0; it < 16; it++) {
                int idx = it * 256 + tid;            // float4 units, 0..4095
                float4 v = __ldcg((const float4*)&hin[idx << 2]);
                int bb = idx >> 7;
                int kq = (idx & 127) << 2;
                *(float4*)&sH[bb * P_H + kq] = v;
            }
            __syncthreads();

            unsigned long long a0 = 0ull, a1 = 0ull, a2 = 0ull;
#pragma unroll 8
            for (int k = 0; k < HID; k += 4) {
                ulonglong2 hh = *(const ulonglong2*)&hb[k];
                ulonglong2 r2 = *(const ulonglong2*)&wr_[k];
                ulonglong2 z2 = *(const ulonglong2*)&wz_[k];
                ulonglong2 n2 = *(const ulonglong2*)&wn_[k];
                ffma2(a0, r2.x, hh.x); ffma2(a0, r2.y, hh.y);
                ffma2(a1, z2.x, hh.x); ffma2(a1, z2.y, hh.y);
                ffma2(a2, n2.x, hh.x); ffma2(a2, n2.y, hh.y);
            }
            float2 f;
            f = unpk(a0); ar = f.x + f.y;
            f = unpk(a1); az = f.x + f.y;
            f = unpk(a2); an = f.x + f.y;
        }

        float r = 1.f / (1.f + expf(-(xr + ar + br)));
        float z = 1.f / (1.f + expf(-(xz + az + bz)));
        float n = tanhf(xn + r * (an + bn));
        float hnew = (1.f - z) * n + z * hold;
        hold = hnew;

        g_h[(s & 1) ^ 1][d][b][j] = hnew;
        g_y[ydst][t][b][d * HID + j] = hnew;

        if (s == T_SEQ - 1) {
            dout[((layer * 2 + d) * BATCH + b) * HID + j] = hnew;
            break;   // nothing consumes h after the last step
        }

        // ---- Grid barrier: per-CTA epoch flags (no atomic serialization) ----
        __syncthreads();                 // all h stores issued; sH reads done
        int e = layer * T_SEQ + s + 1;   // monotonic across layers
        if (tid == 0) {
            __threadfence();             // order this CTA's h stores
            *(volatile int*)&g_flag[d][blockIdx.x] = e;
        }
        // Prefetch next step's Xi while flags propagate
        int tn = d ? (T_SEQ - 2 - s) : (s + 1);
        float nxr = g_xi[d][tn][j][b];
        float nxz = g_xi[d][tn][512 + j][b];
        float nxn = g_xi[d][tn][1024 + j][b];
        if (tid < 64) {
            while (*(volatile int*)&g_flag[d][tid] < e) { }
        }
        __syncthreads();
        __threadfence();                 // acquire: order h reads after flags
        xr = nxr; xz = nxz; xn = nxn;
    }
}

// ---------------------------------------------------------------------------
// kernel_launch: proj0, zero, gru0, proj1, gru1, proj2, gru2
// (7 graph nodes; ncu -s 5 -c 1 lands on proj2 — K=1024, same shape as proj1)
// ---------------------------------------------------------------------------
extern "C" void kernel_launch(void* const* d_in, const int* in_sizes, int n_in,
                              void* d_out, int out_size)
{
    const float* x        = (const float*)d_in[0];
    const float* w_ih_l0  = (const float*)d_in[1];
    const float* w_hh_l0  = (const float*)d_in[2];
    const float* b_ih_l0  = (const float*)d_in[3];
    const float* b_hh_l0  = (const float*)d_in[4];
    const float* w_ih_lr  = (const float*)d_in[5];
    const float* w_hh_lr  = (const float*)d_in[6];
    const float* b_ih_lr  = (const float*)d_in[7];
    const float* b_hh_lr  = (const float*)d_in[8];
    float* out = (float*)d_out;

    cudaFuncSetAttribute(gru_layer_kernel,
                         cudaFuncAttributeMaxDynamicSharedMemorySize, GRU_SMEM);

    const float* WI[LAYERS];
    const float* WH[LAYERS];
    const float* BI[LAYERS];
    const float* BH[LAYERS];
    int KK[LAYERS], SRC[LAYERS], YD[LAYERS];
    for (int L = 0; L < LAYERS; L++) {
        if (L == 0) {
            WI[L] = w_ih_l0; WH[L] = w_hh_l0; BI[L] = b_ih_l0; BH[L] = b_hh_l0;
            KK[L] = 256; SRC[L] = 0;
        } else {
            WI[L] = w_ih_lr + (size_t)(L - 1) * 2 * H3 * 1024;
            WH[L] = w_hh_lr + (size_t)(L - 1) * 2 * H3 * HID;
            BI[L] = b_ih_lr + (L - 1) * 2 * H3;
            BH[L] = b_hh_lr + (L - 1) * 2 * H3;
            KK[L] = 1024; SRC[L] = L;
        }
        YD[L] = (L == 1) ? 1 : 0;   // L0->buf0, L1->buf1, L2->buf0 (unused)
    }

    dim3 pg(H3 / 128, (T_SEQ * BATCH) / 128, 2);

    proj_kernel<<<pg, 512>>>(x, WI[0], BI[0], KK[0], SRC[0]);
    zero_bar_kernel<<<1, 128>>>();
    gru_layer_kernel<<<dim3(64, 2), 256, GRU_SMEM>>>(WH[0], BH[0], out, 0, YD[0]);
    proj_kernel<<<pg, 512>>>(x, WI[1], BI[1], KK[1], SRC[1]);
    gru_layer_kernel<<<dim3(64, 2), 256, GRU_SMEM>>>(WH[1], BH[1], out, 1, YD[1]);
    proj_kernel<<<pg, 512>>>(x, WI[2], BI[2], KK[2], SRC[2]);
    gru_layer_kernel<<<dim3(64, 2), 256, GRU_SMEM>>>(WH[2], BH[2], out, 2, YD[2]);
}

// round 10
// speedup vs baseline: 1.1882x; 1.1882x over previous
#include <cuda_runtime.h>
#include <math.h>

// GRU problem constants
#define T_SEQ 1024
#define BATCH 32
#define HID   512
#define H3    1536   // 3*HID
#define LAYERS 3

// ---------------------------------------------------------------------------
// Scratch (device globals — no runtime allocation allowed)
// ---------------------------------------------------------------------------
__device__ float g_xi[2][T_SEQ][H3][BATCH];     // [dir][t][gate_row][batch]
__device__ float g_y[2][T_SEQ][BATCH][2 * HID]; // layer outputs (2 buffers)
__device__ float g_h[2][2][BATCH][HID];         // h double buffer [buf][dir][b][k]
__device__ int   g_flag[2][4][32];              // [dir][group][cta] epoch flags

// ---------------------------------------------------------------------------
// f32x2 packed-FMA helpers (sm_100+; only reachable via PTX)
// ---------------------------------------------------------------------------
__device__ __forceinline__ unsigned long long dup2(float x) {
    unsigned long long r;
    asm("mov.b64 %0, {%1, %1};" : "=l"(r) : "f"(x));
    return r;
}
__device__ __forceinline__ void ffma2(unsigned long long& d,
                                      unsigned long long a,
                                      unsigned long long b) {
    asm("fma.rn.f32x2 %0, %1, %2, %0;" : "+l"(d) : "l"(a), "l"(b));
}
__device__ __forceinline__ float2 unpk(unsigned long long v) {
    float2 f;
    asm("mov.b64 {%0, %1}, %2;" : "=f"(f.x), "=f"(f.y) : "l"(v));
    return f;
}

// ---------------------------------------------------------------------------
// Zero the flag array (runs once per graph replay, before gru0)
// ---------------------------------------------------------------------------
__global__ void zero_bar_kernel() {
    int i = threadIdx.x;
    if (i < 2 * 4 * 32) ((int*)g_flag)[i] = 0;
}

// ---------------------------------------------------------------------------
// Input projection (unchanged from R9): 128x128 tile, 512 threads,
// 4m x 8j per thread, register double-buffered, f32x2 packed FMA.
// ---------------------------------------------------------------------------
__global__ __launch_bounds__(512) void proj_kernel(
    const float* __restrict__ x0,
    const float* __restrict__ W,      // (2, 1536, K)
    const float* __restrict__ bih,    // (2, 1536)
    int K, int src)
{
    const float* A = (src == 0) ? x0 : &g_y[src - 1][0][0][0];

    int d  = blockIdx.z;
    int n0 = blockIdx.x * 128;  // gate-row tile
    int m0 = blockIdx.y * 128;  // (t,b) row tile
    const float* Wd = W + (size_t)d * H3 * K;
    const float* bd = bih + d * H3;

    __shared__ float As[16][128];
    __shared__ float Bs[16][128];

    int tid = threadIdx.x;
    int tx  = tid & 15;
    int ty  = tid >> 4;

    int lrow = tid >> 2;
    int lq   = (tid & 3) << 2;

    const float* Aptr = &A [(size_t)(m0 + lrow) * K + lq];
    const float* Wptr = &Wd[(size_t)(n0 + lrow) * K + lq];

    unsigned long long acc[4][4];
#pragma unroll
    for (int i = 0; i < 4; i++)
#pragma unroll
        for (int j = 0; j < 4; j++) acc[i][j] = 0ull;

    float4 a_nx = *(const float4*)Aptr;
    float4 b_nx = *(const float4*)Wptr;

    for (int k0 = 0; k0 < K; k0 += 16) {
        As[lq + 0][lrow] = a_nx.x; As[lq + 1][lrow] = a_nx.y;
        As[lq + 2][lrow] = a_nx.z; As[lq + 3][lrow] = a_nx.w;
        Bs[lq + 0][lrow] = b_nx.x; Bs[lq + 1][lrow] = b_nx.y;
        Bs[lq + 2][lrow] = b_nx.z; Bs[lq + 3][lrow] = b_nx.w;
        __syncthreads();

        if (k0 + 16 < K) {
            a_nx = *(const float4*)(Aptr + k0 + 16);
            b_nx = *(const float4*)(Wptr + k0 + 16);
        }

#pragma unroll
        for (int kk = 0; kk < 16; kk++) {
            float4 af = *(const float4*)&As[kk][ty * 4];
            ulonglong2 b0 = *(const ulonglong2*)&Bs[kk][tx * 4];
            ulonglong2 b1 = *(const ulonglong2*)&Bs[kk][64 + tx * 4];
            unsigned long long a0 = dup2(af.x);
            unsigned long long a1 = dup2(af.y);
            unsigned long long a2 = dup2(af.z);
            unsigned long long a3 = dup2(af.w);
            ffma2(acc[0][0], a0, b0.x); ffma2(acc[0][1], a0, b0.y);
            ffma2(acc[0][2], a0, b1.x); ffma2(acc[0][3], a0, b1.y);
            ffma2(acc[1][0], a1, b0.x); ffma2(acc[1][1], a1, b0.y);
            ffma2(acc[1][2], a1, b1.x); ffma2(acc[1][3], a1, b1.y);
            ffma2(acc[2][0], a2, b0.x); ffma2(acc[2][1], a2, b0.y);
            ffma2(acc[2][2], a2, b1.x); ffma2(acc[2][3], a2, b1.y);
            ffma2(acc[3][0], a3, b0.x); ffma2(acc[3][1], a3, b0.y);
            ffma2(acc[3][2], a3, b1.x); ffma2(acc[3][3], a3, b1.y);
        }
        __syncthreads();
    }

#pragma unroll
    for (int i = 0; i < 4; i++) {
        int m = m0 + ty * 4 + i;
        int t = m >> 5;
        int b = m & 31;
#pragma unroll
        for (int jp = 0; jp < 4; jp++) {
            int g = n0 + ((jp < 2) ? (tx * 4 + jp * 2)
                                   : (64 + tx * 4 + (jp - 2) * 2));
            float2 c = unpk(acc[i][jp]);
            g_xi[d][t][g + 0][b] = c.x + bd[g + 0];
            g_xi[d][t][g + 1][b] = c.y + bd[g + 1];
        }
    }
}

// ---------------------------------------------------------------------------
// Persistent recurrent kernel v3 — BATCH-GROUP PARTITION.
// Batches are independent chains: per direction, 4 groups x 8 batches.
// Each group = 16 CTAs; CTA holds a 32-row j-slice of all 3 gates in smem
// (198KB) + the group's 8-row h tile (8x516). Sync domain = 16 CTAs only.
// grid (16 ctas, 4 groups, 2 dirs) = 128 CTAs, 256 threads, 214.5KB smem.
// Lanes: (lb 0..7 = batch-in-group, lj 0..3 = j-row); warp w covers rows
// w*4..w*4+3; W rows pad-516 -> 1 crossbar phase per gate load; h 8 rows
// -> all 32 banks, 1 phase. 4 phases / warp-iter, 2 warps/SMSP.
// ---------------------------------------------------------------------------
#define P_H 516
#define JW  32    // j-rows per CTA per gate
#define GRU_SMEM ((3 * JW * P_H + 8 * P_H) * 4)

__global__ __launch_bounds__(256) void gru_layer_kernel(
    const float* __restrict__ whh,   // (2, 1536, 512)
    const float* __restrict__ bhh,   // (2, 1536)
    float* __restrict__ dout,        // (6, 32, 512)
    int layer, int ydst)
{
    extern __shared__ float sm[];
    float* sW = sm;                  // [3][32][516]
    float* sH = sm + 3 * JW * P_H;   // [8][516]

    int ctax = blockIdx.x;           // 0..15 : j-slice within group
    int grp  = blockIdx.y;           // 0..3  : batch octet
    int d    = blockIdx.z;           // direction
    int tid  = threadIdx.x;
    int w    = tid >> 5;
    int l    = tid & 31;
    int lb   = l & 7;                // batch-in-group
    int lj   = l >> 3;               // j-row-in-quad
    int wj   = w * 4 + lj;           // 0..31 j-row within slice
    int j    = ctax * JW + wj;       // global j
    int b    = grp * 8 + lb;         // global batch

    // ---- Stage W_hh slice: rows {ctax*32 .. +31} x 3 gates (once) ----
    const float* wd = whh + (size_t)d * H3 * HID;
#pragma unroll
    for (int it = 0; it < 48; it++) {
        int idx  = it * 256 + tid;       // float4 units, 0..12287
        int row  = idx >> 7;             // 0..95
        int q    = (idx & 127) << 2;
        int gate = row >> 5;
        int r    = row & 31;
        *(float4*)&sW[(gate * JW + r) * P_H + q] =
            *(const float4*)&wd[(size_t)(gate * 512 + ctax * JW + r) * 512 + q];
    }
    const float* bd = bhh + d * H3;
    float br = bd[j], bz = bd[512 + j], bn = bd[1024 + j];

    const float* wr_ = &sW[(0 * JW + wj) * P_H];
    const float* wz_ = &sW[(1 * JW + wj) * P_H];
    const float* wn_ = &sW[(2 * JW + wj) * P_H];
    const float* hb  = &sH[lb * P_H];
    __syncthreads();

    volatile int* flags = &g_flag[d][grp][0];
    float hold = 0.f;
    int t0 = d ? (T_SEQ - 1) : 0;
    float xr = g_xi[d][t0][j][b];
    float xz = g_xi[d][t0][512 + j][b];
    float xn = g_xi[d][t0][1024 + j][b];

    for (int s = 0; s < T_SEQ; s++) {
        int t = d ? (T_SEQ - 1 - s) : s;

        float ar = 0.f, az = 0.f, an = 0.f;
        if (s > 0) {
            // Stage group's h: 8 rows x 512 = 1024 float4 -> 4 per thread
            const float* hin = &g_h[s & 1][d][grp * 8][0];
#pragma unroll
            for (int it = 0; it < 4; it++) {
                int idx = it * 256 + tid;            // float4 units, 0..1023
                float4 v = __ldcg((const float4*)&hin[idx << 2]);
                int bb = idx >> 7;
                int kq = (idx & 127) << 2;
                *(float4*)&sH[bb * P_H + kq] = v;
            }
            __syncthreads();

            unsigned long long a0 = 0ull, a1 = 0ull, a2 = 0ull;
#pragma unroll 8
            for (int k = 0; k < HID; k += 4) {
                ulonglong2 hh = *(const ulonglong2*)&hb[k];
                ulonglong2 r2 = *(const ulonglong2*)&wr_[k];
                ulonglong2 z2 = *(const ulonglong2*)&wz_[k];
                ulonglong2 n2 = *(const ulonglong2*)&wn_[k];
                ffma2(a0, r2.x, hh.x); ffma2(a0, r2.y, hh.y);
                ffma2(a1, z2.x, hh.x); ffma2(a1, z2.y, hh.y);
                ffma2(a2, n2.x, hh.x); ffma2(a2, n2.y, hh.y);
            }
            float2 f;
            f = unpk(a0); ar = f.x + f.y;
            f = unpk(a1); az = f.x + f.y;
            f = unpk(a2); an = f.x + f.y;
        }

        float r = 1.f / (1.f + expf(-(xr + ar + br)));
        float z = 1.f / (1.f + expf(-(xz + az + bz)));
        float n = tanhf(xn + r * (an + bn));
        float hnew = (1.f - z) * n + z * hold;
        hold = hnew;

        g_h[(s & 1) ^ 1][d][b][j] = hnew;
        g_y[ydst][t][b][d * HID + j] = hnew;

        if (s == T_SEQ - 1) {
            dout[((layer * 2 + d) * BATCH + b) * HID + j] = hnew;
            break;   // nothing consumes h after the last step
        }

        // ---- Group barrier: 16 CTAs, per-CTA epoch flags ----
        __syncthreads();                 // h stores issued; sH reads done
        int e = layer * T_SEQ + s + 1;   // monotonic across layers
        if (tid == 0) {
            __threadfence();             // order this CTA's h stores
            flags[ctax] = e;
        }
        // Prefetch next step's Xi while flags propagate
        int tn = d ? (T_SEQ - 2 - s) : (s + 1);
        float nxr = g_xi[d][tn][j][b];
        float nxz = g_xi[d][tn][512 + j][b];
        float nxn = g_xi[d][tn][1024 + j][b];
        if (tid < 16) {
            while (flags[tid] < e) { }
            __threadfence();             // acquire side
        }
        __syncthreads();
        xr = nxr; xz = nxz; xn = nxn;
    }
}

// ---------------------------------------------------------------------------
// kernel_launch: proj0, zero, zero(dummy), gru0, proj1, gru1, proj2, gru2
// (8 graph nodes; ncu -s 5 -c 1 lands on gru1 — units now understood as ms)
// ---------------------------------------------------------------------------
extern "C" void kernel_launch(void* const* d_in, const int* in_sizes, int n_in,
                              void* d_out, int out_size)
{
    const float* x        = (const float*)d_in[0];
    const float* w_ih_l0  = (const float*)d_in[1];
    const float* w_hh_l0  = (const float*)d_in[2];
    const float* b_ih_l0  = (const float*)d_in[3];
    const float* b_hh_l0  = (const float*)d_in[4];
    const float* w_ih_lr  = (const float*)d_in[5];
    const float* w_hh_lr  = (const float*)d_in[6];
    const float* b_ih_lr  = (const float*)d_in[7];
    const float* b_hh_lr  = (const float*)d_in[8];
    float* out = (float*)d_out;

    cudaFuncSetAttribute(gru_layer_kernel,
                         cudaFuncAttributeMaxDynamicSharedMemorySize, GRU_SMEM);

    const float* WI[LAYERS];
    const float* WH[LAYERS];
    const float* BI[LAYERS];
    const float* BH[LAYERS];
    int KK[LAYERS], SRC[LAYERS], YD[LAYERS];
    for (int L = 0; L < LAYERS; L++) {
        if (L == 0) {
            WI[L] = w_ih_l0; WH[L] = w_hh_l0; BI[L] = b_ih_l0; BH[L] = b_hh_l0;
            KK[L] = 256; SRC[L] = 0;
        } else {
            WI[L] = w_ih_lr + (size_t)(L - 1) * 2 * H3 * 1024;
            WH[L] = w_hh_lr + (size_t)(L - 1) * 2 * H3 * HID;
            BI[L] = b_ih_lr + (L - 1) * 2 * H3;
            BH[L] = b_hh_lr + (L - 1) * 2 * H3;
            KK[L] = 1024; SRC[L] = L;
        }
        YD[L] = (L == 1) ? 1 : 0;   // L0->buf0, L1->buf1, L2->buf0 (unused)
    }

    dim3 pg(H3 / 128, (T_SEQ * BATCH) / 128, 2);
    dim3 gg(16, 4, 2);   // (cta-in-group, group, dir)

    proj_kernel<<<pg, 512>>>(x, WI[0], BI[0], KK[0], SRC[0]);
    zero_bar_kernel<<<1, 256>>>();
    zero_bar_kernel<<<1, 256>>>();   // dummy: aligns ncu -s 5 on gru1

    gru_layer_kernel<<<gg, 256, GRU_SMEM>>>(WH[0], BH[0], out, 0, YD[0]);
    proj_kernel<<<pg, 512>>>(x, WI[1], BI[1], KK[1], SRC[1]);
    gru_layer_kernel<<<gg, 256, GRU_SMEM>>>(WH[1], BH[1], out, 1, YD[1]);
    proj_kernel<<<pg, 512>>>(x, WI[2], BI[2], KK[2], SRC[2]);
    gru_layer_kernel<<<gg, 256, GRU_SMEM>>>(WH[2], BH[2], out, 2, YD[2]);
}

// round 11
// speedup vs baseline: 1.4461x; 1.2171x over previous
#include <cuda_runtime.h>
#include <math.h>

// GRU problem constants
#define T_SEQ 1024
#define BATCH 32
#define HID   512
#define H3    1536   // 3*HID
#define LAYERS 3

// ---------------------------------------------------------------------------
// Scratch (device globals — no runtime allocation allowed)
// ---------------------------------------------------------------------------
__device__ float g_xi[2][T_SEQ][H3][BATCH];     // [dir][t][gate_row][batch]
__device__ float g_y[2][T_SEQ][BATCH][2 * HID]; // layer outputs (2 buffers)
__device__ float g_h[2][2][BATCH][HID];         // h double buffer [buf][dir][b][k]
__device__ int   g_flag[2][4][32];              // [dir][group][cta] epoch flags

typedef unsigned long long ull;

// ---------------------------------------------------------------------------
// f32x2 packed-FMA helpers (sm_100+; only reachable via PTX)
// ---------------------------------------------------------------------------
__device__ __forceinline__ ull dup2(float x) {
    ull r;
    asm("mov.b64 %0, {%1, %1};" : "=l"(r) : "f"(x));
    return r;
}
__device__ __forceinline__ void ffma2(ull& d, ull a, ull b) {
    asm("fma.rn.f32x2 %0, %1, %2, %0;" : "+l"(d) : "l"(a), "l"(b));
}
__device__ __forceinline__ float2 unpk(ull v) {
    float2 f;
    asm("mov.b64 {%0, %1}, %2;" : "=f"(f.x), "=f"(f.y) : "l"(v));
    return f;
}

// ---------------------------------------------------------------------------
// Zero the flag array (runs once per graph replay, before gru0)
// ---------------------------------------------------------------------------
__global__ void zero_bar_kernel() {
    int i = threadIdx.x;
    if (i < 2 * 4 * 32) ((int*)g_flag)[i] = 0;
}

// ---------------------------------------------------------------------------
// Input projection (unchanged): 128x128 tile, 512 threads, 4m x 8j per
// thread, register double-buffered global loads, f32x2 packed FMA.
// ---------------------------------------------------------------------------
__global__ __launch_bounds__(512) void proj_kernel(
    const float* __restrict__ x0,
    const float* __restrict__ W,      // (2, 1536, K)
    const float* __restrict__ bih,    // (2, 1536)
    int K, int src)
{
    const float* A = (src == 0) ? x0 : &g_y[src - 1][0][0][0];

    int d  = blockIdx.z;
    int n0 = blockIdx.x * 128;
    int m0 = blockIdx.y * 128;
    const float* Wd = W + (size_t)d * H3 * K;
    const float* bd = bih + d * H3;

    __shared__ float As[16][128];
    __shared__ float Bs[16][128];

    int tid = threadIdx.x;
    int tx  = tid & 15;
    int ty  = tid >> 4;

    int lrow = tid >> 2;
    int lq   = (tid & 3) << 2;

    const float* Aptr = &A [(size_t)(m0 + lrow) * K + lq];
    const float* Wptr = &Wd[(size_t)(n0 + lrow) * K + lq];

    ull acc[4][4];
#pragma unroll
    for (int i = 0; i < 4; i++)
#pragma unroll
        for (int j = 0; j < 4; j++) acc[i][j] = 0ull;

    float4 a_nx = *(const float4*)Aptr;
    float4 b_nx = *(const float4*)Wptr;

    for (int k0 = 0; k0 < K; k0 += 16) {
        As[lq + 0][lrow] = a_nx.x; As[lq + 1][lrow] = a_nx.y;
        As[lq + 2][lrow] = a_nx.z; As[lq + 3][lrow] = a_nx.w;
        Bs[lq + 0][lrow] = b_nx.x; Bs[lq + 1][lrow] = b_nx.y;
        Bs[lq + 2][lrow] = b_nx.z; Bs[lq + 3][lrow] = b_nx.w;
        __syncthreads();

        if (k0 + 16 < K) {
            a_nx = *(const float4*)(Aptr + k0 + 16);
            b_nx = *(const float4*)(Wptr + k0 + 16);
        }

#pragma unroll
        for (int kk = 0; kk < 16; kk++) {
            float4 af = *(const float4*)&As[kk][ty * 4];
            ulonglong2 b0 = *(const ulonglong2*)&Bs[kk][tx * 4];
            ulonglong2 b1 = *(const ulonglong2*)&Bs[kk][64 + tx * 4];
            ull a0 = dup2(af.x);
            ull a1 = dup2(af.y);
            ull a2 = dup2(af.z);
            ull a3 = dup2(af.w);
            ffma2(acc[0][0], a0, b0.x); ffma2(acc[0][1], a0, b0.y);
            ffma2(acc[0][2], a0, b1.x); ffma2(acc[0][3], a0, b1.y);
            ffma2(acc[1][0], a1, b0.x); ffma2(acc[1][1], a1, b0.y);
            ffma2(acc[1][2], a1, b1.x); ffma2(acc[1][3], a1, b1.y);
            ffma2(acc[2][0], a2, b0.x); ffma2(acc[2][1], a2, b0.y);
            ffma2(acc[2][2], a2, b1.x); ffma2(acc[2][3], a2, b1.y);
            ffma2(acc[3][0], a3, b0.x); ffma2(acc[3][1], a3, b0.y);
            ffma2(acc[3][2], a3, b1.x); ffma2(acc[3][3], a3, b1.y);
        }
        __syncthreads();
    }

#pragma unroll
    for (int i = 0; i < 4; i++) {
        int m = m0 + ty * 4 + i;
        int t = m >> 5;
        int b = m & 31;
#pragma unroll
        for (int jp = 0; jp < 4; jp++) {
            int g = n0 + ((jp < 2) ? (tx * 4 + jp * 2)
                                   : (64 + tx * 4 + (jp - 2) * 2));
            float2 c = unpk(acc[i][jp]);
            g_xi[d][t][g + 0][b] = c.x + bd[g + 0];
            g_xi[d][t][g + 1][b] = c.y + bd[g + 1];
        }
    }
}

// ---------------------------------------------------------------------------
// Persistent recurrent kernel v4 — REGISTER-RESIDENT W_hh.
// grid (16 j-slices, 4 groups, 2 dirs) = 128 CTAs (1/SM), 256 threads.
// Warp w covers j-quad {w*4..w*4+3}; lane = lks*4+lj.
// Thread owns W[3 gates][j = base+lj][k in {lks*4 + 32*i, i=0..15}] = 192 regs
// (strided k-slices -> the warp's h LDS.128 covers contiguous 128B, 1 phase).
// Per step per b: 16x(LDS.128 + 6 FFMA2); partials reduced over lks via
// shfl_xor (masks 4/8/16); lane keeps the b matching its lks -> epilogue
// mapping (j = w*4+lj, b = lks) covers all (j,b) with no smem round-trip.
// W never touches the crossbar after load: ~8000 -> ~1200 phases/step.
// ---------------------------------------------------------------------------
__global__ __launch_bounds__(256) void gru_layer_kernel(
    const float* __restrict__ whh,   // (2, 1536, 512)
    const float* __restrict__ bhh,   // (2, 1536)
    float* __restrict__ dout,        // (6, 32, 512)
    int layer, int ydst)
{
    __shared__ float sH[8 * HID];    // 16KB h staging [b_in_group][k]

    int ctax = blockIdx.x;           // 0..15 : j-slice (32 j each)
    int grp  = blockIdx.y;           // 0..3  : batch octet
    int d    = blockIdx.z;           // direction
    int tid  = threadIdx.x;
    int w    = tid >> 5;
    int l    = tid & 31;
    int lj   = l & 3;                // j-row within quad
    int lks  = l >> 2;               // k-slice 0..7
    int j    = ctax * 32 + w * 4 + lj;   // global j (this thread's row)
    int b_ep = grp * 8 + lks;        // epilogue batch

    // ---- Load W_hh into registers (once per layer) ----
    // Thread's k set: {lks*4 + 32*i + 0..3 : i = 0..15}  (64 floats per gate)
    ull Wr[32], Wz[32], Wn[32];
    {
        const float* wd = whh + (size_t)d * H3 * HID;
        const float* pr = &wd[(size_t)(0 * 512 + j) * 512 + lks * 4];
        const float* pz = &wd[(size_t)(1 * 512 + j) * 512 + lks * 4];
        const float* pn = &wd[(size_t)(2 * 512 + j) * 512 + lks * 4];
#pragma unroll
        for (int i = 0; i < 16; i++) {
            ulonglong2 v;
            v = *(const ulonglong2*)&pr[i * 32];
            Wr[2 * i] = v.x; Wr[2 * i + 1] = v.y;
            v = *(const ulonglong2*)&pz[i * 32];
            Wz[2 * i] = v.x; Wz[2 * i + 1] = v.y;
            v = *(const ulonglong2*)&pn[i * 32];
            Wn[2 * i] = v.x; Wn[2 * i + 1] = v.y;
        }
    }
    const float* bd = bhh + d * H3;
    float br = bd[j], bz = bd[512 + j], bn = bd[1024 + j];

    volatile int* flags = &g_flag[d][grp][0];
    float hold = 0.f;
    int t0 = d ? (T_SEQ - 1) : 0;
    float xr = g_xi[d][t0][j][b_ep];
    float xz = g_xi[d][t0][512 + j][b_ep];
    float xn = g_xi[d][t0][1024 + j][b_ep];

    for (int s = 0; s < T_SEQ; s++) {
        int t = d ? (T_SEQ - 1 - s) : s;

        float arS = 0.f, azS = 0.f, anS = 0.f;
        if (s > 0) {
            // Stage group's h: 8 rows x 512 = 1024 float4 -> 4 per thread
            const float* hin = &g_h[s & 1][d][grp * 8][0];
#pragma unroll
            for (int it = 0; it < 4; it++) {
                int idx = it * 256 + tid;            // float4 units, 0..1023
                float4 v = __ldcg((const float4*)&hin[idx << 2]);
                *(float4*)&sH[idx << 2] = v;
            }
            __syncthreads();

            // GEMV: for each batch, partial over this thread's k-slice,
            // then butterfly-reduce over lks; keep the b == lks result.
            for (int b = 0; b < 8; b++) {
                const float* hp = &sH[b * HID + lks * 4];
                ull a0 = 0ull, a1 = 0ull, a2 = 0ull;
#pragma unroll
                for (int i = 0; i < 16; i++) {
                    ulonglong2 hh = *(const ulonglong2*)&hp[i * 32];
                    ffma2(a0, Wr[2 * i], hh.x); ffma2(a0, Wr[2 * i + 1], hh.y);
                    ffma2(a1, Wz[2 * i], hh.x); ffma2(a1, Wz[2 * i + 1], hh.y);
                    ffma2(a2, Wn[2 * i], hh.x); ffma2(a2, Wn[2 * i + 1], hh.y);
                }
                float2 f0 = unpk(a0), f1 = unpk(a1), f2 = unpk(a2);
                float ar = f0.x + f0.y;
                float az = f1.x + f1.y;
                float an = f2.x + f2.y;
#pragma unroll
                for (int m = 4; m <= 16; m <<= 1) {
                    ar += __shfl_xor_sync(0xffffffffu, ar, m);
                    az += __shfl_xor_sync(0xffffffffu, az, m);
                    an += __shfl_xor_sync(0xffffffffu, an, m);
                }
                if (lks == b) { arS = ar; azS = az; anS = an; }
            }
        }

        float r = 1.f / (1.f + expf(-(xr + arS + br)));
        float z = 1.f / (1.f + expf(-(xz + azS + bz)));
        float n = tanhf(xn + r * (anS + bn));
        float hnew = (1.f - z) * n + z * hold;
        hold = hnew;

        g_h[(s & 1) ^ 1][d][b_ep][j] = hnew;
        g_y[ydst][t][b_ep][d * HID + j] = hnew;

        if (s == T_SEQ - 1) {
            dout[((layer * 2 + d) * BATCH + b_ep) * HID + j] = hnew;
            break;   // nothing consumes h after the last step
        }

        // ---- Group barrier: 16 CTAs, per-CTA epoch flags ----
        __syncthreads();                 // h stores issued; sH reads done
        int e = layer * T_SEQ + s + 1;   // monotonic across layers
        if (tid == 0) {
            __threadfence();             // order this CTA's h stores
            flags[ctax] = e;
        }
        // Prefetch next step's Xi while flags propagate
        int tn = d ? (T_SEQ - 2 - s) : (s + 1);
        float nxr = g_xi[d][tn][j][b_ep];
        float nxz = g_xi[d][tn][512 + j][b_ep];
        float nxn = g_xi[d][tn][1024 + j][b_ep];
        if (tid < 16) {
            while (flags[tid] < e) { }
            __threadfence();             // acquire side
        }
        __syncthreads();
        xr = nxr; xz = nxz; xn = nxn;
    }
}

// ---------------------------------------------------------------------------
// kernel_launch: proj0, zero, zero(dummy), gru0, proj1, gru1, proj2, gru2
// (8 graph nodes; ncu -s 5 -c 1 lands on gru1)
// ---------------------------------------------------------------------------
extern "C" void kernel_launch(void* const* d_in, const int* in_sizes, int n_in,
                              void* d_out, int out_size)
{
    const float* x        = (const float*)d_in[0];
    const float* w_ih_l0  = (const float*)d_in[1];
    const float* w_hh_l0  = (const float*)d_in[2];
    const float* b_ih_l0  = (const float*)d_in[3];
    const float* b_hh_l0  = (const float*)d_in[4];
    const float* w_ih_lr  = (const float*)d_in[5];
    const float* w_hh_lr  = (const float*)d_in[6];
    const float* b_ih_lr  = (const float*)d_in[7];
    const float* b_hh_lr  = (const float*)d_in[8];
    float* out = (float*)d_out;

    const float* WI[LAYERS];
    const float* WH[LAYERS];
    const float* BI[LAYERS];
    const float* BH[LAYERS];
    int KK[LAYERS], SRC[LAYERS], YD[LAYERS];
    for (int L = 0; L < LAYERS; L++) {
        if (L == 0) {
            WI[L] = w_ih_l0; WH[L] = w_hh_l0; BI[L] = b_ih_l0; BH[L] = b_hh_l0;
            KK[L] = 256; SRC[L] = 0;
        } else {
            WI[L] = w_ih_lr + (size_t)(L - 1) * 2 * H3 * 1024;
            WH[L] = w_hh_lr + (size_t)(L - 1) * 2 * H3 * HID;
            BI[L] = b_ih_lr + (L - 1) * 2 * H3;
            BH[L] = b_hh_lr + (L - 1) * 2 * H3;
            KK[L] = 1024; SRC[L] = L;
        }
        YD[L] = (L == 1) ? 1 : 0;   // L0->buf0, L1->buf1, L2->buf0 (unused)
    }

    dim3 pg(H3 / 128, (T_SEQ * BATCH) / 128, 2);
    dim3 gg(16, 4, 2);   // (j-slice, group, dir)

    proj_kernel<<<pg, 512>>>(x, WI[0], BI[0], KK[0], SRC[0]);
    zero_bar_kernel<<<1, 256>>>();
    zero_bar_kernel<<<1, 256>>>();   // dummy: aligns ncu -s 5 on gru1

    gru_layer_kernel<<<gg, 256>>>(WH[0], BH[0], out, 0, YD[0]);
    proj_kernel<<<pg, 512>>>(x, WI[1], BI[1], KK[1], SRC[1]);
    gru_layer_kernel<<<gg, 256>>>(WH[1], BH[1], out, 1, YD[1]);
    proj_kernel<<<pg, 512>>>(x, WI[2], BI[2], KK[2], SRC[2]);
    gru_layer_kernel<<<gg, 256>>>(WH[2], BH[2], out, 2, YD[2]);
}

// round 12
// speedup vs baseline: 1.4767x; 1.0212x over previous
#include <cuda_runtime.h>
#include <math.h>

// GRU problem constants
#define T_SEQ 1024
#define BATCH 32
#define HID   512
#define H3    1536   // 3*HID
#define LAYERS 3

// ---------------------------------------------------------------------------
// Scratch (device globals — no runtime allocation allowed)
// ---------------------------------------------------------------------------
__device__ float g_xi[2][T_SEQ][H3][BATCH];     // [dir][t][gate_row][batch]
__device__ float g_y[2][T_SEQ][BATCH][2 * HID]; // layer outputs (2 buffers)
__device__ float g_h[2][2][BATCH][HID];         // h double buffer [buf][dir][b][k]
__device__ int   g_flag[2][4][32];              // [dir][group][cta] epoch flags

typedef unsigned long long ull;

// ---------------------------------------------------------------------------
// f32x2 packed-FMA helpers (sm_100+; only reachable via PTX)
// ---------------------------------------------------------------------------
__device__ __forceinline__ ull dup2(float x) {
    ull r;
    asm("mov.b64 %0, {%1, %1};" : "=l"(r) : "f"(x));
    return r;
}
__device__ __forceinline__ void ffma2(ull& d, ull a, ull b) {
    asm("fma.rn.f32x2 %0, %1, %2, %0;" : "+l"(d) : "l"(a), "l"(b));
}
__device__ __forceinline__ float2 unpk(ull v) {
    float2 f;
    asm("mov.b64 {%0, %1}, %2;" : "=f"(f.x), "=f"(f.y) : "l"(v));
    return f;
}
// Butterfly-reduce a packed accumulator over the 8 k-slices (lanes xor 4/8/16)
__device__ __forceinline__ float red_ks(ull a) {
    float2 f = unpk(a);
    float v = f.x + f.y;
    v += __shfl_xor_sync(0xffffffffu, v, 4);
    v += __shfl_xor_sync(0xffffffffu, v, 8);
    v += __shfl_xor_sync(0xffffffffu, v, 16);
    return v;
}

// ---------------------------------------------------------------------------
// Zero the flag array (runs once per graph replay, before gru0)
// ---------------------------------------------------------------------------
__global__ void zero_bar_kernel() {
    int i = threadIdx.x;
    if (i < 2 * 4 * 32) ((int*)g_flag)[i] = 0;
}

// ---------------------------------------------------------------------------
// Input projection v3: 128x128 tile, 256 threads, 8m x 8j per thread,
// register double-buffered global loads, f32x2 packed FMA.
// No min-blocks cap: ~130 regs, no spills, 8 warps/SM.
// Per kk: 6 LDS wavefronts per 64 fma-cycles (was 5 per 32) -> L1 relief.
// ---------------------------------------------------------------------------
__global__ __launch_bounds__(256) void proj_kernel(
    const float* __restrict__ x0,
    const float* __restrict__ W,      // (2, 1536, K)
    const float* __restrict__ bih,    // (2, 1536)
    int K, int src)
{
    const float* A = (src == 0) ? x0 : &g_y[src - 1][0][0][0];

    int d  = blockIdx.z;
    int n0 = blockIdx.x * 128;  // gate-row tile
    int m0 = blockIdx.y * 128;  // (t,b) row tile
    const float* Wd = W + (size_t)d * H3 * K;
    const float* bd = bih + d * H3;

    __shared__ float As[16][128];
    __shared__ float Bs[16][128];

    int tid = threadIdx.x;
    int tx  = tid & 15;
    int ty  = tid >> 4;

    // Staging: 512 float4 per array per k0 -> 2 per thread
    int i0   = tid;             // idx = i*256 + tid
    int lrow0 = i0 >> 2,        lq0 = (i0 & 3) << 2;
    int i1   = 256 + tid;
    int lrow1 = i1 >> 2,        lq1 = (i1 & 3) << 2;

    const float* Ap0 = &A [(size_t)(m0 + lrow0) * K + lq0];
    const float* Ap1 = &A [(size_t)(m0 + lrow1) * K + lq1];
    const float* Wp0 = &Wd[(size_t)(n0 + lrow0) * K + lq0];
    const float* Wp1 = &Wd[(size_t)(n0 + lrow1) * K + lq1];

    ull acc[8][4];
#pragma unroll
    for (int i = 0; i < 8; i++)
#pragma unroll
        for (int j = 0; j < 4; j++) acc[i][j] = 0ull;

    float4 a0_nx = *(const float4*)Ap0;
    float4 a1_nx = *(const float4*)Ap1;
    float4 b0_nx = *(const float4*)Wp0;
    float4 b1_nx = *(const float4*)Wp1;

    for (int k0 = 0; k0 < K; k0 += 16) {
        As[lq0 + 0][lrow0] = a0_nx.x; As[lq0 + 1][lrow0] = a0_nx.y;
        As[lq0 + 2][lrow0] = a0_nx.z; As[lq0 + 3][lrow0] = a0_nx.w;
        As[lq1 + 0][lrow1] = a1_nx.x; As[lq1 + 1][lrow1] = a1_nx.y;
        As[lq1 + 2][lrow1] = a1_nx.z; As[lq1 + 3][lrow1] = a1_nx.w;
        Bs[lq0 + 0][lrow0] = b0_nx.x; Bs[lq0 + 1][lrow0] = b0_nx.y;
        Bs[lq0 + 2][lrow0] = b0_nx.z; Bs[lq0 + 3][lrow0] = b0_nx.w;
        Bs[lq1 + 0][lrow1] = b1_nx.x; Bs[lq1 + 1][lrow1] = b1_nx.y;
        Bs[lq1 + 2][lrow1] = b1_nx.z; Bs[lq1 + 3][lrow1] = b1_nx.w;
        __syncthreads();

        if (k0 + 16 < K) {
            a0_nx = *(const float4*)(Ap0 + k0 + 16);
            a1_nx = *(const float4*)(Ap1 + k0 + 16);
            b0_nx = *(const float4*)(Wp0 + k0 + 16);
            b1_nx = *(const float4*)(Wp1 + k0 + 16);
        }

#pragma unroll
        for (int kk = 0; kk < 16; kk++) {
            float4 af0 = *(const float4*)&As[kk][ty * 4];
            float4 af1 = *(const float4*)&As[kk][64 + ty * 4];
            ulonglong2 b0 = *(const ulonglong2*)&Bs[kk][tx * 4];
            ulonglong2 b1 = *(const ulonglong2*)&Bs[kk][64 + tx * 4];
            ull aa[8];
            aa[0] = dup2(af0.x); aa[1] = dup2(af0.y);
            aa[2] = dup2(af0.z); aa[3] = dup2(af0.w);
            aa[4] = dup2(af1.x); aa[5] = dup2(af1.y);
            aa[6] = dup2(af1.z); aa[7] = dup2(af1.w);
#pragma unroll
            for (int i = 0; i < 8; i++) {
                ffma2(acc[i][0], aa[i], b0.x);
                ffma2(acc[i][1], aa[i], b0.y);
                ffma2(acc[i][2], aa[i], b1.x);
                ffma2(acc[i][3], aa[i], b1.y);
            }
        }
        __syncthreads();
    }

#pragma unroll
    for (int i = 0; i < 8; i++) {
        int m = m0 + ((i < 4) ? (ty * 4 + i) : (64 + ty * 4 + (i - 4)));
        int t = m >> 5;
        int b = m & 31;
#pragma unroll
        for (int jp = 0; jp < 4; jp++) {
            int g = n0 + ((jp < 2) ? (tx * 4 + jp * 2)
                                   : (64 + tx * 4 + (jp - 2) * 2));
            float2 c = unpk(acc[i][jp]);
            g_xi[d][t][g + 0][b] = c.x + bd[g + 0];
            g_xi[d][t][g + 1][b] = c.y + bd[g + 1];
        }
    }
}

// ---------------------------------------------------------------------------
// Persistent recurrent kernel v5 — reg-resident W_hh + PIPELINED SPLIT-K
// EXCHANGE. Producer ctax writes k-range [32*ctax, 32*ctax+32) of h, so the
// consumer waits flags[0..7] -> stage k<256 -> GEMV(i<8), then flags[8..15]
// -> stage k>=256 -> GEMV(i>=8): the hi half's wait+load latency hides
// behind the lo half's compute. Waits moved to TOP of step (safe: a CTA
// writes h(s+1) only after waiting all 16 flags >= base+s during step s,
// so every CTA has finished reading the target buffer).
// ---------------------------------------------------------------------------
__global__ __launch_bounds__(256) void gru_layer_kernel(
    const float* __restrict__ whh,   // (2, 1536, 512)
    const float* __restrict__ bhh,   // (2, 1536)
    float* __restrict__ dout,        // (6, 32, 512)
    int layer, int ydst)
{
    __shared__ float sH[8 * HID];    // 16KB h staging [b_in_group][k]

    int ctax = blockIdx.x;           // 0..15 : j-slice (32 j each)
    int grp  = blockIdx.y;           // 0..3  : batch octet
    int d    = blockIdx.z;           // direction
    int tid  = threadIdx.x;
    int w    = tid >> 5;
    int l    = tid & 31;
    int lj   = l & 3;                // j-row within quad
    int lks  = l >> 2;               // k-slice 0..7
    int j    = ctax * 32 + w * 4 + lj;
    int b_ep = grp * 8 + lks;        // epilogue batch

    // ---- Load W_hh into registers (once per layer) ----
    ull Wr[32], Wz[32], Wn[32];
    {
        const float* wd = whh + (size_t)d * H3 * HID;
        const float* pr = &wd[(size_t)(0 * 512 + j) * 512 + lks * 4];
        const float* pz = &wd[(size_t)(1 * 512 + j) * 512 + lks * 4];
        const float* pn = &wd[(size_t)(2 * 512 + j) * 512 + lks * 4];
#pragma unroll
        for (int i = 0; i < 16; i++) {
            ulonglong2 v;
            v = *(const ulonglong2*)&pr[i * 32];
            Wr[2 * i] = v.x; Wr[2 * i + 1] = v.y;
            v = *(const ulonglong2*)&pz[i * 32];
            Wz[2 * i] = v.x; Wz[2 * i + 1] = v.y;
            v = *(const ulonglong2*)&pn[i * 32];
            Wn[2 * i] = v.x; Wn[2 * i + 1] = v.y;
        }
    }
    const float* bd = bhh + d * H3;
    float br = bd[j], bz = bd[512 + j], bn = bd[1024 + j];

    volatile int* flags = &g_flag[d][grp][0];
    int ebase = layer * T_SEQ;
    float hold = 0.f;
    int t0 = d ? (T_SEQ - 1) : 0;
    float xr = g_xi[d][t0][j][b_ep];
    float xz = g_xi[d][t0][512 + j][b_ep];
    float xn = g_xi[d][t0][1024 + j][b_ep];

    for (int s = 0; s < T_SEQ; s++) {
        int t = d ? (T_SEQ - 1 - s) : s;

        float arS = 0.f, azS = 0.f, anS = 0.f;
        if (s > 0) {
            int we = ebase + s;                      // h(s) ready epoch
            const float* hin = &g_h[s & 1][d][grp * 8][0];

            // ---- half LO: k in [0,256) (producers ctax 0..7) ----
            if (tid < 8) {
                while (flags[tid] < we) { }
                __threadfence();
            }
            __syncthreads();
#pragma unroll
            for (int it = 0; it < 2; it++) {
                int idx = it * 256 + tid;            // 0..511
                int bb = idx >> 6, q = idx & 63;     // q*4 = k < 256
                float4 v = __ldcg((const float4*)&hin[(bb * 128 + q) << 2]);
                *(float4*)&sH[(bb * 128 + q) << 2] = v;
            }
            __syncthreads();
#pragma unroll 2
            for (int b = 0; b < 8; b++) {
                const float* hp = &sH[b * HID + lks * 4];
                ull a0 = 0ull, a1 = 0ull, a2 = 0ull;
#pragma unroll
                for (int i = 0; i < 8; i++) {
                    ulonglong2 hh = *(const ulonglong2*)&hp[i * 32];
                    ffma2(a0, Wr[2 * i], hh.x); ffma2(a0, Wr[2 * i + 1], hh.y);
                    ffma2(a1, Wz[2 * i], hh.x); ffma2(a1, Wz[2 * i + 1], hh.y);
                    ffma2(a2, Wn[2 * i], hh.x); ffma2(a2, Wn[2 * i + 1], hh.y);
                }
                float vr = red_ks(a0), vz = red_ks(a1), vn = red_ks(a2);
                if (lks == b) { arS += vr; azS += vz; anS += vn; }
            }

            // ---- half HI: k in [256,512) (producers ctax 8..15) ----
            if (tid < 8) {
                while (flags[8 + tid] < we) { }
                __threadfence();
            }
            __syncthreads();
#pragma unroll
            for (int it = 0; it < 2; it++) {
                int idx = it * 256 + tid;
                int bb = idx >> 6, q = 64 + (idx & 63);   // k >= 256
                float4 v = __ldcg((const float4*)&hin[(bb * 128 + q) << 2]);
                *(float4*)&sH[(bb * 128 + q) << 2] = v;
            }
            __syncthreads();
#pragma unroll 2
            for (int b = 0; b < 8; b++) {
                const float* hp = &sH[b * HID + lks * 4];
                ull a0 = 0ull, a1 = 0ull, a2 = 0ull;
#pragma unroll
                for (int i = 8; i < 16; i++) {
                    ulonglong2 hh = *(const ulonglong2*)&hp[i * 32];
                    ffma2(a0, Wr[2 * i], hh.x); ffma2(a0, Wr[2 * i + 1], hh.y);
                    ffma2(a1, Wz[2 * i], hh.x); ffma2(a1, Wz[2 * i + 1], hh.y);
                    ffma2(a2, Wn[2 * i], hh.x); ffma2(a2, Wn[2 * i + 1], hh.y);
                }
                float vr = red_ks(a0), vz = red_ks(a1), vn = red_ks(a2);
                if (lks == b) { arS += vr; azS += vz; anS += vn; }
            }
        }

        float r = 1.f / (1.f + expf(-(xr + arS + br)));
        float z = 1.f / (1.f + expf(-(xz + azS + bz)));
        float n = tanhf(xn + r * (anS + bn));
        float hnew = (1.f - z) * n + z * hold;
        hold = hnew;

        g_h[(s & 1) ^ 1][d][b_ep][j] = hnew;
        g_y[ydst][t][b_ep][d * HID + j] = hnew;

        if (s == T_SEQ - 1) {
            dout[((layer * 2 + d) * BATCH + b_ep) * HID + j] = hnew;
            break;   // nothing consumes h after the last step
        }

        // ---- Post readiness flag (wait happens at top of next step) ----
        __syncthreads();                 // all warps' h stores issued
        if (tid == 0) {
            __threadfence();             // order this CTA's h stores
            flags[ctax] = ebase + s + 1;
        }
        // Prefetch next step's Xi (overlaps next step's lo-wait)
        int tn = d ? (T_SEQ - 2 - s) : (s + 1);
        float nxr = g_xi[d][tn][j][b_ep];
        float nxz = g_xi[d][tn][512 + j][b_ep];
        float nxn = g_xi[d][tn][1024 + j][b_ep];
        xr = nxr; xz = nxz; xn = nxn;
    }
}

// ---------------------------------------------------------------------------
// kernel_launch: proj0, zero, zero(dummy), gru0, proj1, gru1, proj2, gru2
// (8 graph nodes; ncu -s 5 -c 1 lands on gru1)
// ---------------------------------------------------------------------------
extern "C" void kernel_launch(void* const* d_in, const int* in_sizes, int n_in,
                              void* d_out, int out_size)
{
    const float* x        = (const float*)d_in[0];
    const float* w_ih_l0  = (const float*)d_in[1];
    const float* w_hh_l0  = (const float*)d_in[2];
    const float* b_ih_l0  = (const float*)d_in[3];
    const float* b_hh_l0  = (const float*)d_in[4];
    const float* w_ih_lr  = (const float*)d_in[5];
    const float* w_hh_lr  = (const float*)d_in[6];
    const float* b_ih_lr  = (const float*)d_in[7];
    const float* b_hh_lr  = (const float*)d_in[8];
    float* out = (float*)d_out;

    const float* WI[LAYERS];
    const float* WH[LAYERS];
    const float* BI[LAYERS];
    const float* BH[LAYERS];
    int KK[LAYERS], SRC[LAYERS], YD[LAYERS];
    for (int L = 0; L < LAYERS; L++) {
        if (L == 0) {
            WI[L] = w_ih_l0; WH[L] = w_hh_l0; BI[L] = b_ih_l0; BH[L] = b_hh_l0;
            KK[L] = 256; SRC[L] = 0;
        } else {
            WI[L] = w_ih_lr + (size_t)(L - 1) * 2 * H3 * 1024;
            WH[L] = w_hh_lr + (size_t)(L - 1) * 2 * H3 * HID;
            BI[L] = b_ih_lr + (L - 1) * 2 * H3;
            BH[L] = b_hh_lr + (L - 1) * 2 * H3;
            KK[L] = 1024; SRC[L] = L;
        }
        YD[L] = (L == 1) ? 1 : 0;   // L0->buf0, L1->buf1, L2->buf0 (unused)
    }

    dim3 pg(H3 / 128, (T_SEQ * BATCH) / 128, 2);
    dim3 gg(16, 4, 2);   // (j-slice, group, dir)

    proj_kernel<<<pg, 256>>>(x, WI[0], BI[0], KK[0], SRC[0]);
    zero_bar_kernel<<<1, 256>>>();
    zero_bar_kernel<<<1, 256>>>();   // dummy: aligns ncu -s 5 on gru1

    gru_layer_kernel<<<gg, 256>>>(WH[0], BH[0], out, 0, YD[0]);
    proj_kernel<<<pg, 256>>>(x, WI[1], BI[1], KK[1], SRC[1]);
    gru_layer_kernel<<<gg, 256>>>(WH[1], BH[1], out, 1, YD[1]);
    proj_kernel<<<pg, 256>>>(x, WI[2], BI[2], KK[2], SRC[2]);
    gru_layer_kernel<<<gg, 256>>>(WH[2], BH[2], out, 2, YD[2]);
}